// round 3
// baseline (speedup 1.0000x reference)
#include <cuda_runtime.h>
#include <math.h>

#define BB 32
#define TT 1024
#define II 512
#define HH 512
#define G4 2048      // 4*H
#define GRID_P 128   // persistent CTAs (<=148 -> co-resident, deadlock-free)

typedef unsigned long long u64t;

// ---- packed fp32x2 helpers (Blackwell FFMA2) ----
__device__ __forceinline__ u64t ffma2(u64t a, u64t b, u64t c) {
    u64t d;
    asm("fma.rn.f32x2 %0, %1, %2, %3;" : "=l"(d) : "l"(a), "l"(b), "l"(c));
    return d;
}
__device__ __forceinline__ u64t pack2(float x, float y) {
    u64t d;
    asm("mov.b64 %0, {%1, %2};" : "=l"(d) : "f"(x), "f"(y));
    return d;
}
__device__ __forceinline__ float2 unpack2(u64t v) {
    float2 r;
    asm("mov.b64 {%0, %1}, %2;" : "=f"(r.x), "=f"(r.y) : "l"(v));
    return r;
}

// ---------------- scratch (static device globals; no allocation) ----------------
__device__ float    g_xpre[(size_t)BB * TT * G4];   // [B][T][4H]  256 MB
__device__ float    g_hT[2][HH * BB];               // double-buffered h^T [j][b]
__device__ unsigned g_flags[GRID_P];                // per-CTA barrier flags

// ---------------- Kernel 0: init (reset flags, h0 -> h_T buffer 0) ----------------
__global__ void init_kernel(const float* __restrict__ h0)
{
    int i = blockIdx.x * 256 + threadIdx.x;
    if (i < BB * HH) {
        int b = i >> 9;
        int j = i & 511;
        g_hT[0][j * BB + b] = h0[i];
    }
    if (i < GRID_P) g_flags[i] = 0;
}

// ---------------- Kernel 1: x_pre = x @ [Wii|Wif|Wio|Wig] + bias ----------------
// Tiled FP32 SGEMM (FFMA2): 128x128 tile, K-step 8, 256 threads, 8x8 per thread.
__global__ __launch_bounds__(256) void gemm_x_kernel(
    const float* __restrict__ X,
    const float* __restrict__ Wii, const float* __restrict__ Wif,
    const float* __restrict__ Wio, const float* __restrict__ Wig,
    const float* __restrict__ bi, const float* __restrict__ bf,
    const float* __restrict__ bo, const float* __restrict__ bg,
    float* __restrict__ xpre)
{
    const int mtile = blockIdx.x;          // 0..255
    const int gtile = blockIdx.y;          // 0..15
    const int gate  = gtile >> 2;
    const int j0    = (gtile & 3) * 128;

    const float* W    = (gate == 0) ? Wii : (gate == 1) ? Wif : (gate == 2) ? Wio : Wig;
    const float* bias = (gate == 0) ? bi  : (gate == 1) ? bf  : (gate == 2) ? bo  : bg;

    __shared__ float As[8][132];
    __shared__ float Bs[8][128];

    const int tid = threadIdx.x;
    const int tx = tid & 15;
    const int ty = tid >> 4;
    const int m0 = mtile * 128;

    const int a_row = tid >> 1;
    const int a_k   = (tid & 1) * 4;
    const int b_k = tid >> 5;
    const int b_n = (tid & 31) * 4;

    u64t acc2[8][4];
#pragma unroll
    for (int i = 0; i < 8; i++)
#pragma unroll
        for (int j = 0; j < 4; j++) acc2[i][j] = 0ull;

    for (int k0 = 0; k0 < 512; k0 += 8) {
        float4 av = *(const float4*)(X + (size_t)(m0 + a_row) * 512 + k0 + a_k);
        As[a_k + 0][a_row] = av.x;
        As[a_k + 1][a_row] = av.y;
        As[a_k + 2][a_row] = av.z;
        As[a_k + 3][a_row] = av.w;
        float4 bv = *(const float4*)(W + (size_t)(k0 + b_k) * 512 + j0 + b_n);
        *(float4*)&Bs[b_k][b_n] = bv;
        __syncthreads();

#pragma unroll
        for (int kk = 0; kk < 8; kk++) {
            float4 a0 = *(const float4*)&As[kk][ty * 8];
            float4 a1 = *(const float4*)&As[kk][ty * 8 + 4];
            u64t arr[8];
            arr[0] = pack2(a0.x, a0.x); arr[1] = pack2(a0.y, a0.y);
            arr[2] = pack2(a0.z, a0.z); arr[3] = pack2(a0.w, a0.w);
            arr[4] = pack2(a1.x, a1.x); arr[5] = pack2(a1.y, a1.y);
            arr[6] = pack2(a1.z, a1.z); arr[7] = pack2(a1.w, a1.w);
            ulonglong2 bb0 = *(const ulonglong2*)&Bs[kk][tx * 8];
            ulonglong2 bb1 = *(const ulonglong2*)&Bs[kk][tx * 8 + 4];
            u64t br2[4];
            br2[0] = bb0.x; br2[1] = bb0.y; br2[2] = bb1.x; br2[3] = bb1.y;
#pragma unroll
            for (int i = 0; i < 8; i++)
#pragma unroll
                for (int j = 0; j < 4; j++)
                    acc2[i][j] = ffma2(arr[i], br2[j], acc2[i][j]);
        }
        __syncthreads();
    }

#pragma unroll
    for (int i = 0; i < 8; i++) {
        const size_t m = (size_t)(m0 + ty * 8 + i);
        float* dst = xpre + m * G4 + gate * 512 + j0 + tx * 8;
        float4 o0, o1;
        float2 p0 = unpack2(acc2[i][0]);
        float2 p1 = unpack2(acc2[i][1]);
        float2 p2 = unpack2(acc2[i][2]);
        float2 p3 = unpack2(acc2[i][3]);
        o0.x = p0.x + bias[j0 + tx * 8 + 0];
        o0.y = p0.y + bias[j0 + tx * 8 + 1];
        o0.z = p1.x + bias[j0 + tx * 8 + 2];
        o0.w = p1.y + bias[j0 + tx * 8 + 3];
        o1.x = p2.x + bias[j0 + tx * 8 + 4];
        o1.y = p2.y + bias[j0 + tx * 8 + 5];
        o1.z = p3.x + bias[j0 + tx * 8 + 6];
        o1.w = p3.y + bias[j0 + tx * 8 + 7];
        *(float4*)dst       = o0;
        *(float4*)(dst + 4) = o1;
    }
}

// ---------------- Kernel 2: persistent recurrence ----------------
// 128 CTAs x 256 threads. CTA owns 4 h-columns jc..jc+3 -> 16 gate-cols = 8 col-pairs.
// Warp w handles ALL 8 pairs over k-slice [w*64, w*64+64). FFMA2 packed math.
// Weights pair-interleaved in SMEM: sh_w[p*1024 + k*2 + {lo,hi}].
//
// SMEM layout (floats):
#define SH_H  0                       // h[k][b]               512*32 = 16384
#define SH_W  (SH_H  + 512*32)        // w pairs               8*512*2 = 8192
#define SH_PS (SH_W  + 8*1024)        // partials [w][p][b][2] 8*8*32*2 = 4096
#define SH_XS (SH_PS + 8*512)         // xpre [q][b][jj]       4*32*4 = 512
#define SH_C  (SH_XS + 4*32*4)        // cell [jj][b]          128
#define SH_HO (SH_C  + 4*32)          // h out [b][jj]         128
#define SH_TOTAL_FLOATS (SH_HO + 32*4)

extern __shared__ float smem_p[];

__global__ __launch_bounds__(256, 1) void lstm_persist_kernel(
    const float* __restrict__ xpre,
    const float* __restrict__ Whi, const float* __restrict__ Whf,
    const float* __restrict__ Who, const float* __restrict__ Whg,
    const float* __restrict__ c0,
    float* __restrict__ out,
    int write_tail)
{
    float* sh_h  = smem_p + SH_H;
    float* sh_w  = smem_p + SH_W;
    float* sh_ps = smem_p + SH_PS;
    float* sh_xs = smem_p + SH_XS;
    float* sh_c  = smem_p + SH_C;
    float* sh_ho = smem_p + SH_HO;

    const int tid  = threadIdx.x;
    const int lane = tid & 31;
    const int w    = tid >> 5;
    const int jc   = blockIdx.x * 4;        // h-column base

    // ---- one-time: load weight slice, pair-interleaved ----
    // pair p = q*2 + pp covers gate q, cols (jc+2pp, jc+2pp+1)
    for (int e = tid; e < 8 * 1024; e += 256) {
        int p    = e >> 10;
        int rem  = e & 1023;
        int k    = rem >> 1;
        int half = rem & 1;
        int q    = p >> 1;
        int pp   = p & 1;
        const float* Wq = (q == 0) ? Whi : (q == 1) ? Whf : (q == 2) ? Who : Whg;
        sh_w[p * 1024 + k * 2 + half] = Wq[(size_t)k * HH + jc + pp * 2 + half];
    }
    // ---- one-time: init cell state slice ----
    if (tid < 128) {
        int jj = tid >> 5;
        int b  = tid & 31;
        sh_c[jj * 32 + b] = c0[b * HH + jc + jj];
    }
    __syncthreads();

    const int kb = w * 64;      // this warp's k-slice

    for (int t = 0; t < TT; ++t) {
        const float* hT_r = g_hT[t & 1];
        float*       hT_w = g_hT[(t + 1) & 1];

        // ---- stage h (coalesced float4) and xpre slice ----
        {
            const float4* src = (const float4*)hT_r;
            float4* dst = (float4*)sh_h;
#pragma unroll
            for (int i = 0; i < 16; i++)
                dst[tid + i * 256] = src[tid + i * 256];
        }
        if (tid < 128) {
            int b = tid >> 2;
            int q = tid & 3;
            float4 v = *(const float4*)(xpre + ((size_t)b * TT + t) * G4 + q * 512 + jc);
            *(float4*)(sh_xs + (q * 32 + b) * 4) = v;
        }
        __syncthreads();

        // ---- recurrent GEMM slice (FFMA2, 8 col-pairs x k-slice 64) ----
        u64t acc[8];
#pragma unroll
        for (int p = 0; p < 8; p++) acc[p] = 0ull;

#pragma unroll 4
        for (int k = kb; k < kb + 64; k += 2) {
            float h0 = sh_h[k * 32 + lane];
            float h1 = sh_h[(k + 1) * 32 + lane];
            u64t hh0 = pack2(h0, h0);
            u64t hh1 = pack2(h1, h1);
#pragma unroll
            for (int p = 0; p < 8; p++) {
                ulonglong2 wv = *(const ulonglong2*)&sh_w[p * 1024 + k * 2];
                acc[p] = ffma2(hh0, wv.x, acc[p]);
                acc[p] = ffma2(hh1, wv.y, acc[p]);
            }
        }
#pragma unroll
        for (int p = 0; p < 8; p++)
            *(u64t*)&sh_ps[w * 512 + p * 64 + lane * 2] = acc[p];
        __syncthreads();

        // ---- gates + state update (128 threads: jj x b) ----
        if (tid < 128) {
            int jj = tid >> 5;
            int b  = tid & 31;
            float v[4];
#pragma unroll
            for (int q = 0; q < 4; q++) {
                int p    = q * 2 + (jj >> 1);
                int half = jj & 1;
                float s = sh_xs[(q * 32 + b) * 4 + jj];
#pragma unroll
                for (int w8 = 0; w8 < 8; w8++)
                    s += sh_ps[w8 * 512 + p * 64 + b * 2 + half];
                v[q] = s;
            }
            float it = 1.0f / (1.0f + expf(-v[0]));
            float ft = 1.0f / (1.0f + expf(-v[1]));
            float ot = 1.0f / (1.0f + expf(-v[2]));
            float gt = tanhf(v[3]);
            float cn = ft * sh_c[jj * 32 + b] + it * gt;
            float hn = ot * tanhf(cn);
            sh_c[jj * 32 + b] = cn;
            sh_ho[b * 4 + jj] = hn;
            hT_w[(jc + jj) * BB + b] = hn;     // coalesced 128B per jj
        }
        __syncthreads();

        // ---- output write (float4 per batch) ----
        if (tid < 32) {
            int b = tid;
            *(float4*)(out + ((size_t)b * TT + t) * HH + jc) = *(float4*)(sh_ho + b * 4);
        }

        // ---- grid barrier: per-CTA flags, warp-0 polls ----
        if (tid == 0) {
            __threadfence();
            *(volatile unsigned*)&g_flags[blockIdx.x] = (unsigned)(t + 1);
        }
        if (tid < 32) {
            volatile unsigned* f0 = &g_flags[tid];
            volatile unsigned* f1 = &g_flags[tid + 32];
            volatile unsigned* f2 = &g_flags[tid + 64];
            volatile unsigned* f3 = &g_flags[tid + 96];
            const unsigned t1 = (unsigned)(t + 1);
            for (;;) {
                unsigned a = *f0, b = *f1, c = *f2, d = *f3;
                if (a >= t1 && b >= t1 && c >= t1 && d >= t1) break;
            }
            __threadfence();
        }
        __syncthreads();
    }

    // ---- final (h_t, c_t) tail ----
    if (write_tail && tid < 128) {
        int jj = tid >> 5;
        int b  = tid & 31;
        const size_t tail = (size_t)BB * TT * HH;
        out[tail + (size_t)b * HH + jc + jj]                   = sh_ho[b * 4 + jj];
        out[tail + (size_t)BB * HH + (size_t)b * HH + jc + jj] = sh_c[jj * 32 + b];
    }
}

// ---------------- launch ----------------
extern "C" void kernel_launch(void* const* d_in, const int* in_sizes, int n_in,
                              void* d_out, int out_size) {
    const float* x   = (const float*)d_in[0];
    const float* h0  = (const float*)d_in[1];
    const float* c0  = (const float*)d_in[2];
    const float* Wii = (const float*)d_in[3];
    const float* Wif = (const float*)d_in[4];
    const float* Wio = (const float*)d_in[5];
    const float* Wig = (const float*)d_in[6];
    const float* Whi = (const float*)d_in[7];
    const float* Whf = (const float*)d_in[8];
    const float* Who = (const float*)d_in[9];
    const float* Whg = (const float*)d_in[10];
    const float* bi  = (const float*)d_in[11];
    const float* bf_ = (const float*)d_in[12];
    const float* bo  = (const float*)d_in[13];
    const float* bg  = (const float*)d_in[14];
    float* out = (float*)d_out;

    float* xpre;
    cudaGetSymbolAddress((void**)&xpre, g_xpre);

    const size_t smem_bytes = SH_TOTAL_FLOATS * sizeof(float);
    cudaFuncSetAttribute(lstm_persist_kernel,
                         cudaFuncAttributeMaxDynamicSharedMemorySize,
                         (int)smem_bytes);

    const long long tail = (long long)BB * TT * HH;
    const int write_tail = ((long long)out_size >= tail + 2LL * BB * HH) ? 1 : 0;

    init_kernel<<<64, 256>>>(h0);
    gemm_x_kernel<<<dim3(256, 16), 256>>>(x, Wii, Wif, Wio, Wig, bi, bf_, bo, bg, xpre);
    lstm_persist_kernel<<<GRID_P, 256, smem_bytes>>>(
        xpre, Whi, Whf, Who, Whg, c0, out, write_tail);
}

// round 4
// speedup vs baseline: 1.8132x; 1.8132x over previous
#include <cuda_runtime.h>
#include <math.h>

#define BB 32
#define TT 1024
#define II 512
#define HH 512
#define G4 2048      // 4*H
#define GRID_P 128   // persistent CTAs (<=148 -> co-resident, deadlock-free)

typedef unsigned long long u64t;

// ---- packed fp32x2 helpers (Blackwell FFMA2) ----
__device__ __forceinline__ u64t ffma2(u64t a, u64t b, u64t c) {
    u64t d;
    asm("fma.rn.f32x2 %0, %1, %2, %3;" : "=l"(d) : "l"(a), "l"(b), "l"(c));
    return d;
}
__device__ __forceinline__ u64t pack2(float x, float y) {
    u64t d;
    asm("mov.b64 %0, {%1, %2};" : "=l"(d) : "f"(x), "f"(y));
    return d;
}
__device__ __forceinline__ float2 unpack2(u64t v) {
    float2 r;
    asm("mov.b64 {%0, %1}, %2;" : "=f"(r.x), "=f"(r.y) : "l"(v));
    return r;
}

// ---------------- scratch (static device globals; no allocation) ----------------
__device__ float    g_xpre[(size_t)BB * TT * G4];   // [B][T][4H]  256 MB
__device__ float    g_hT[2][HH * BB];               // double-buffered h^T [j][b]
__device__ unsigned g_bar_count;
__device__ unsigned g_bar_phase;

// ---------------- Kernel 1: x_pre = x @ [Wii|Wif|Wio|Wig] + bias ----------------
// Tiled FP32 SGEMM (FFMA2): 128x128 tile, K-step 8, 256 threads, 8x8 per thread.
// Block (0,0) additionally performs the init work (h0 -> hT[0], barrier reset).
__global__ __launch_bounds__(256) void gemm_x_kernel(
    const float* __restrict__ X,
    const float* __restrict__ Wii, const float* __restrict__ Wif,
    const float* __restrict__ Wio, const float* __restrict__ Wig,
    const float* __restrict__ bi, const float* __restrict__ bf,
    const float* __restrict__ bo, const float* __restrict__ bg,
    const float* __restrict__ h0,
    float* __restrict__ xpre)
{
    const int mtile = blockIdx.x;          // 0..255
    const int gtile = blockIdx.y;          // 0..15
    const int gate  = gtile >> 2;
    const int j0    = (gtile & 3) * 128;

    // ---- merged init (one block) ----
    if (mtile == 0 && gtile == 0) {
        for (int i = threadIdx.x; i < BB * HH; i += 256) {
            int b = i >> 9;
            int j = i & 511;
            g_hT[0][j * BB + b] = h0[i];
        }
        if (threadIdx.x == 0) { g_bar_count = 0; g_bar_phase = 0; }
    }

    const float* W    = (gate == 0) ? Wii : (gate == 1) ? Wif : (gate == 2) ? Wio : Wig;
    const float* bias = (gate == 0) ? bi  : (gate == 1) ? bf  : (gate == 2) ? bo  : bg;

    __shared__ float As[8][132];
    __shared__ float Bs[8][128];

    const int tid = threadIdx.x;
    const int tx = tid & 15;
    const int ty = tid >> 4;
    const int m0 = mtile * 128;

    const int a_row = tid >> 1;
    const int a_k   = (tid & 1) * 4;
    const int b_k = tid >> 5;
    const int b_n = (tid & 31) * 4;

    u64t acc2[8][4];
#pragma unroll
    for (int i = 0; i < 8; i++)
#pragma unroll
        for (int j = 0; j < 4; j++) acc2[i][j] = 0ull;

    for (int k0 = 0; k0 < 512; k0 += 8) {
        float4 av = *(const float4*)(X + (size_t)(m0 + a_row) * 512 + k0 + a_k);
        As[a_k + 0][a_row] = av.x;
        As[a_k + 1][a_row] = av.y;
        As[a_k + 2][a_row] = av.z;
        As[a_k + 3][a_row] = av.w;
        float4 bv = *(const float4*)(W + (size_t)(k0 + b_k) * 512 + j0 + b_n);
        *(float4*)&Bs[b_k][b_n] = bv;
        __syncthreads();

#pragma unroll
        for (int kk = 0; kk < 8; kk++) {
            float4 a0 = *(const float4*)&As[kk][ty * 8];
            float4 a1 = *(const float4*)&As[kk][ty * 8 + 4];
            u64t arr[8];
            arr[0] = pack2(a0.x, a0.x); arr[1] = pack2(a0.y, a0.y);
            arr[2] = pack2(a0.z, a0.z); arr[3] = pack2(a0.w, a0.w);
            arr[4] = pack2(a1.x, a1.x); arr[5] = pack2(a1.y, a1.y);
            arr[6] = pack2(a1.z, a1.z); arr[7] = pack2(a1.w, a1.w);
            ulonglong2 bb0 = *(const ulonglong2*)&Bs[kk][tx * 8];
            ulonglong2 bb1 = *(const ulonglong2*)&Bs[kk][tx * 8 + 4];
            u64t br2[4];
            br2[0] = bb0.x; br2[1] = bb0.y; br2[2] = bb1.x; br2[3] = bb1.y;
#pragma unroll
            for (int i = 0; i < 8; i++)
#pragma unroll
                for (int j = 0; j < 4; j++)
                    acc2[i][j] = ffma2(arr[i], br2[j], acc2[i][j]);
        }
        __syncthreads();
    }

#pragma unroll
    for (int i = 0; i < 8; i++) {
        const size_t m = (size_t)(m0 + ty * 8 + i);
        float* dst = xpre + m * G4 + gate * 512 + j0 + tx * 8;
        float4 o0, o1;
        float2 p0 = unpack2(acc2[i][0]);
        float2 p1 = unpack2(acc2[i][1]);
        float2 p2 = unpack2(acc2[i][2]);
        float2 p3 = unpack2(acc2[i][3]);
        o0.x = p0.x + bias[j0 + tx * 8 + 0];
        o0.y = p0.y + bias[j0 + tx * 8 + 1];
        o0.z = p1.x + bias[j0 + tx * 8 + 2];
        o0.w = p1.y + bias[j0 + tx * 8 + 3];
        o1.x = p2.x + bias[j0 + tx * 8 + 4];
        o1.y = p2.y + bias[j0 + tx * 8 + 5];
        o1.z = p3.x + bias[j0 + tx * 8 + 6];
        o1.w = p3.y + bias[j0 + tx * 8 + 7];
        *(float4*)dst       = o0;
        *(float4*)(dst + 4) = o1;
    }
}

// ---------------- Kernel 2: persistent recurrence ----------------
// 128 CTAs x 256 threads. CTA owns 4 h-cols jc..jc+3 -> 16 gate-cols = 8 col-pairs.
// Warp w: all 8 pairs over k-slice [w*64, w*64+64). h read DIRECTLY from gmem
// (per-warp slices are disjoint; no intra-CTA reuse -> no staging). FFMA2 math.
//
// SMEM layout (floats):
#define SH_W  0                       // w pairs               8*512*2 = 8192
#define SH_PS (SH_W  + 8*1024)        // partials [w][p][b][2] 8*8*32*2 = 4096
#define SH_XS (SH_PS + 8*512)         // xpre [q][b][jj]       4*32*4 = 512
#define SH_C  (SH_XS + 4*32*4)        // cell [jj][b]          128
#define SH_HO (SH_C  + 4*32)          // h out [b][jj]         128
#define SH_TOTAL_FLOATS (SH_HO + 32*4)

extern __shared__ float smem_p[];

__global__ __launch_bounds__(256, 1) void lstm_persist_kernel(
    const float* __restrict__ xpre,
    const float* __restrict__ Whi, const float* __restrict__ Whf,
    const float* __restrict__ Who, const float* __restrict__ Whg,
    const float* __restrict__ c0,
    float* __restrict__ out,
    int write_tail)
{
    float* sh_w  = smem_p + SH_W;
    float* sh_ps = smem_p + SH_PS;
    float* sh_xs = smem_p + SH_XS;
    float* sh_c  = smem_p + SH_C;
    float* sh_ho = smem_p + SH_HO;

    const int tid  = threadIdx.x;
    const int lane = tid & 31;
    const int w    = tid >> 5;
    const int jc   = blockIdx.x * 4;        // h-column base

    // ---- one-time: load weight slice, pair-interleaved ----
    for (int e = tid; e < 8 * 1024; e += 256) {
        int p    = e >> 10;
        int rem  = e & 1023;
        int k    = rem >> 1;
        int half = rem & 1;
        int q    = p >> 1;
        int pp   = p & 1;
        const float* Wq = (q == 0) ? Whi : (q == 1) ? Whf : (q == 2) ? Who : Whg;
        sh_w[p * 1024 + k * 2 + half] = Wq[(size_t)k * HH + jc + pp * 2 + half];
    }
    if (tid < 128) {
        int jj = tid >> 5;
        int b  = tid & 31;
        sh_c[jj * 32 + b] = c0[b * HH + jc + jj];
    }
    __syncthreads();

    const int kb = w * 64;      // this warp's k-slice

    // gates-phase decomposition for tid<128
    const int g_jj = tid >> 5;
    const int g_b  = tid & 31;
    // xpre prefetch mapping for tid<128
    const int x_b = tid >> 2;
    const int x_q = tid & 3;

    float4 xnext;
    if (tid < 128)
        xnext = *(const float4*)(xpre + ((size_t)x_b * TT + 0) * G4 + x_q * 512 + jc);

    for (int t = 0; t < TT; ++t) {
        const float* hT_r = g_hT[t & 1];
        float*       hT_w = g_hT[(t + 1) & 1];

        // ---- commit staged xpre; prefetch next ----
        if (tid < 128) {
            *(float4*)(sh_xs + (x_q * 32 + x_b) * 4) = xnext;
            if (t + 1 < TT)
                xnext = *(const float4*)(xpre + ((size_t)x_b * TT + t + 1) * G4 + x_q * 512 + jc);
        }

        // ---- recurrent GEMM slice: h via direct LDG, weights via SMEM bcast ----
        const float* hp = hT_r + (size_t)kb * 32 + lane;
        u64t acc[8];
#pragma unroll
        for (int p = 0; p < 8; p++) acc[p] = 0ull;

#pragma unroll
        for (int c = 0; c < 8; c++) {           // 8 chunks of 8 k
            float hr[8];
#pragma unroll
            for (int i = 0; i < 8; i++)
                hr[i] = hp[(c * 8 + i) * 32];
#pragma unroll
            for (int i = 0; i < 8; i += 2) {
                const int k = kb + c * 8 + i;
                u64t hh0 = pack2(hr[i],     hr[i]);
                u64t hh1 = pack2(hr[i + 1], hr[i + 1]);
#pragma unroll
                for (int p = 0; p < 8; p++) {
                    ulonglong2 wv = *(const ulonglong2*)&sh_w[p * 1024 + k * 2];
                    acc[p] = ffma2(hh0, wv.x, acc[p]);
                    acc[p] = ffma2(hh1, wv.y, acc[p]);
                }
            }
        }
#pragma unroll
        for (int p = 0; p < 8; p++)
            *(u64t*)&sh_ps[w * 512 + p * 64 + lane * 2] = acc[p];
        __syncthreads();

        // ---- gates + state update (128 threads: jj x b) ----
        if (tid < 128) {
            const int jj = g_jj, b = g_b;
            float v[4];
#pragma unroll
            for (int q = 0; q < 4; q++) {
                int p    = q * 2 + (jj >> 1);
                int half = jj & 1;
                float s = sh_xs[(q * 32 + b) * 4 + jj];
#pragma unroll
                for (int w8 = 0; w8 < 8; w8++)
                    s += sh_ps[w8 * 512 + p * 64 + b * 2 + half];
                v[q] = s;
            }
            float it = 1.0f / (1.0f + expf(-v[0]));
            float ft = 1.0f / (1.0f + expf(-v[1]));
            float ot = 1.0f / (1.0f + expf(-v[2]));
            float gt = tanhf(v[3]);
            float cn = ft * sh_c[jj * 32 + b] + it * gt;
            float hn = ot * tanhf(cn);
            sh_c[jj * 32 + b] = cn;
            sh_ho[b * 4 + jj] = hn;
            hT_w[(jc + jj) * BB + b] = hn;     // coalesced 128B per jj
        }
        __syncthreads();

        // ---- arrival, output write, poll (warp 0) ----
        if (tid == 0) {
            __threadfence();
            unsigned a = atomicAdd(&g_bar_count, 1u);
            if (a == (unsigned)(GRID_P - 1)) {
                g_bar_count = 0;
                __threadfence();
                *(volatile unsigned*)&g_bar_phase = (unsigned)(t + 1);
            }
        }
        if (tid < 32) {
            int b = tid;
            *(float4*)(out + ((size_t)b * TT + t) * HH + jc) = *(float4*)(sh_ho + b * 4);
        }
        if (tid == 0) {
            while (*(volatile unsigned*)&g_bar_phase <= (unsigned)t)
                __nanosleep(32);
            __threadfence();
        }
        __syncthreads();
    }

    // ---- final (h_t, c_t) tail ----
    if (write_tail && tid < 128) {
        int jj = tid >> 5;
        int b  = tid & 31;
        const size_t tail = (size_t)BB * TT * HH;
        out[tail + (size_t)b * HH + jc + jj]                   = sh_ho[b * 4 + jj];
        out[tail + (size_t)BB * HH + (size_t)b * HH + jc + jj] = sh_c[jj * 32 + b];
    }
}

// ---------------- launch ----------------
extern "C" void kernel_launch(void* const* d_in, const int* in_sizes, int n_in,
                              void* d_out, int out_size) {
    const float* x   = (const float*)d_in[0];
    const float* h0  = (const float*)d_in[1];
    const float* c0  = (const float*)d_in[2];
    const float* Wii = (const float*)d_in[3];
    const float* Wif = (const float*)d_in[4];
    const float* Wio = (const float*)d_in[5];
    const float* Wig = (const float*)d_in[6];
    const float* Whi = (const float*)d_in[7];
    const float* Whf = (const float*)d_in[8];
    const float* Who = (const float*)d_in[9];
    const float* Whg = (const float*)d_in[10];
    const float* bi  = (const float*)d_in[11];
    const float* bf_ = (const float*)d_in[12];
    const float* bo  = (const float*)d_in[13];
    const float* bg  = (const float*)d_in[14];
    float* out = (float*)d_out;

    float* xpre;
    cudaGetSymbolAddress((void**)&xpre, g_xpre);

    const size_t smem_bytes = SH_TOTAL_FLOATS * sizeof(float);
    cudaFuncSetAttribute(lstm_persist_kernel,
                         cudaFuncAttributeMaxDynamicSharedMemorySize,
                         (int)smem_bytes);

    const long long tail = (long long)BB * TT * HH;
    const int write_tail = ((long long)out_size >= tail + 2LL * BB * HH) ? 1 : 0;

    gemm_x_kernel<<<dim3(256, 16), 256>>>(x, Wii, Wif, Wio, Wig, bi, bf_, bo, bg, h0, xpre);
    lstm_persist_kernel<<<GRID_P, 256, smem_bytes>>>(
        xpre, Whi, Whf, Who, Whg, c0, out, write_tail);
}

// round 5
// speedup vs baseline: 1.8335x; 1.0112x over previous
#include <cuda_runtime.h>
#include <math.h>

#define BB 32
#define TT 1024
#define II 512
#define HH 512
#define G4 2048      // 4*H
#define GRID_P 128   // persistent CTAs (<=148 -> co-resident, deadlock-free)

typedef unsigned long long u64t;

// ---- packed fp32x2 helpers (Blackwell FFMA2) ----
__device__ __forceinline__ u64t ffma2(u64t a, u64t b, u64t c) {
    u64t d;
    asm("fma.rn.f32x2 %0, %1, %2, %3;" : "=l"(d) : "l"(a), "l"(b), "l"(c));
    return d;
}
__device__ __forceinline__ u64t pack2(float x, float y) {
    u64t d;
    asm("mov.b64 %0, {%1, %2};" : "=l"(d) : "f"(x), "f"(y));
    return d;
}
__device__ __forceinline__ float2 unpack2(u64t v) {
    float2 r;
    asm("mov.b64 {%0, %1}, %2;" : "=f"(r.x), "=f"(r.y) : "l"(v));
    return r;
}

// ---------------- scratch (static device globals; no allocation) ----------------
__device__ float    g_xpre[(size_t)BB * TT * G4];   // [B][T][4H]  256 MB
__device__ float    g_hT[2][HH * BB];               // double-buffered h^T [j][b]
__device__ unsigned g_bar_count;
__device__ unsigned g_bar_phase;

// ---------------- Kernel 1: x_pre = x @ [Wii|Wif|Wio|Wig] + bias ----------------
// Tiled FP32 SGEMM (FFMA2), double-buffered SMEM + register prefetch.
// 128x128 tile, K-step 8, 256 threads, 8x8 per thread.
// Block (0,0) additionally performs the init work (h0 -> hT[0], barrier reset).
__global__ __launch_bounds__(256) void gemm_x_kernel(
    const float* __restrict__ X,
    const float* __restrict__ Wii, const float* __restrict__ Wif,
    const float* __restrict__ Wio, const float* __restrict__ Wig,
    const float* __restrict__ bi, const float* __restrict__ bf,
    const float* __restrict__ bo, const float* __restrict__ bg,
    const float* __restrict__ h0,
    float* __restrict__ xpre)
{
    const int mtile = blockIdx.x;          // 0..255
    const int gtile = blockIdx.y;          // 0..15
    const int gate  = gtile >> 2;
    const int j0    = (gtile & 3) * 128;

    // ---- merged init (one block) ----
    if (mtile == 0 && gtile == 0) {
        for (int i = threadIdx.x; i < BB * HH; i += 256) {
            int b = i >> 9;
            int j = i & 511;
            g_hT[0][j * BB + b] = h0[i];
        }
        if (threadIdx.x == 0) { g_bar_count = 0; g_bar_phase = 0; }
    }

    const float* W    = (gate == 0) ? Wii : (gate == 1) ? Wif : (gate == 2) ? Wio : Wig;
    const float* bias = (gate == 0) ? bi  : (gate == 1) ? bf  : (gate == 2) ? bo  : bg;

    __shared__ float As[2][8][132];
    __shared__ float Bs[2][8][128];

    const int tid = threadIdx.x;
    const int tx = tid & 15;
    const int ty = tid >> 4;
    const int m0 = mtile * 128;

    const int a_row = tid >> 1;
    const int a_k   = (tid & 1) * 4;
    const int b_k = tid >> 5;
    const int b_n = (tid & 31) * 4;

    u64t acc2[8][4];
#pragma unroll
    for (int i = 0; i < 8; i++)
#pragma unroll
        for (int j = 0; j < 4; j++) acc2[i][j] = 0ull;

    // prologue: load tile 0 into buffer 0
    {
        float4 av = *(const float4*)(X + (size_t)(m0 + a_row) * 512 + a_k);
        As[0][a_k + 0][a_row] = av.x;
        As[0][a_k + 1][a_row] = av.y;
        As[0][a_k + 2][a_row] = av.z;
        As[0][a_k + 3][a_row] = av.w;
        float4 bv = *(const float4*)(W + (size_t)b_k * 512 + j0 + b_n);
        *(float4*)&Bs[0][b_k][b_n] = bv;
    }
    __syncthreads();

    for (int k0 = 0; k0 < 512; k0 += 8) {
        const int cur = (k0 >> 3) & 1;
        const int nxt = cur ^ 1;

        // register-prefetch next tile (overlaps with compute below)
        float4 av, bv;
        const bool more = (k0 + 8 < 512);
        if (more) {
            av = *(const float4*)(X + (size_t)(m0 + a_row) * 512 + k0 + 8 + a_k);
            bv = *(const float4*)(W + (size_t)(k0 + 8 + b_k) * 512 + j0 + b_n);
        }

#pragma unroll
        for (int kk = 0; kk < 8; kk++) {
            float4 a0 = *(const float4*)&As[cur][kk][ty * 8];
            float4 a1 = *(const float4*)&As[cur][kk][ty * 8 + 4];
            u64t arr[8];
            arr[0] = pack2(a0.x, a0.x); arr[1] = pack2(a0.y, a0.y);
            arr[2] = pack2(a0.z, a0.z); arr[3] = pack2(a0.w, a0.w);
            arr[4] = pack2(a1.x, a1.x); arr[5] = pack2(a1.y, a1.y);
            arr[6] = pack2(a1.z, a1.z); arr[7] = pack2(a1.w, a1.w);
            ulonglong2 bb0 = *(const ulonglong2*)&Bs[cur][kk][tx * 8];
            ulonglong2 bb1 = *(const ulonglong2*)&Bs[cur][kk][tx * 8 + 4];
            u64t br2[4];
            br2[0] = bb0.x; br2[1] = bb0.y; br2[2] = bb1.x; br2[3] = bb1.y;
#pragma unroll
            for (int i = 0; i < 8; i++)
#pragma unroll
                for (int j = 0; j < 4; j++)
                    acc2[i][j] = ffma2(arr[i], br2[j], acc2[i][j]);
        }

        if (more) {
            As[nxt][a_k + 0][a_row] = av.x;
            As[nxt][a_k + 1][a_row] = av.y;
            As[nxt][a_k + 2][a_row] = av.z;
            As[nxt][a_k + 3][a_row] = av.w;
            *(float4*)&Bs[nxt][b_k][b_n] = bv;
        }
        __syncthreads();
    }

#pragma unroll
    for (int i = 0; i < 8; i++) {
        const size_t m = (size_t)(m0 + ty * 8 + i);
        float* dst = xpre + m * G4 + gate * 512 + j0 + tx * 8;
        float4 o0, o1;
        float2 p0 = unpack2(acc2[i][0]);
        float2 p1 = unpack2(acc2[i][1]);
        float2 p2 = unpack2(acc2[i][2]);
        float2 p3 = unpack2(acc2[i][3]);
        o0.x = p0.x + bias[j0 + tx * 8 + 0];
        o0.y = p0.y + bias[j0 + tx * 8 + 1];
        o0.z = p1.x + bias[j0 + tx * 8 + 2];
        o0.w = p1.y + bias[j0 + tx * 8 + 3];
        o1.x = p2.x + bias[j0 + tx * 8 + 4];
        o1.y = p2.y + bias[j0 + tx * 8 + 5];
        o1.z = p3.x + bias[j0 + tx * 8 + 6];
        o1.w = p3.y + bias[j0 + tx * 8 + 7];
        *(float4*)dst       = o0;
        *(float4*)(dst + 4) = o1;
    }
}

// ---------------- Kernel 2: persistent recurrence ----------------
// 128 CTAs x 256 threads. CTA owns 4 h-cols jc..jc+3 -> 16 gate-cols = 8 col-pairs.
// Warp w: all 8 pairs over k-slice [w*64, w*64+64). The warp's FULL 64-float h
// slice is preloaded into registers (front-batched LDGs -> one latency exposure),
// then a pure FFMA2 + LDS-broadcast stream. Weights SMEM-resident all 1024 steps.
//
// SMEM layout (floats):
#define SH_W  0                       // w pairs               8*512*2 = 8192
#define SH_PS (SH_W  + 8*1024)        // partials [w][p][b][2] 8*8*32*2 = 4096
#define SH_XS (SH_PS + 8*512)         // xpre [q][b][jj]       4*32*4 = 512
#define SH_C  (SH_XS + 4*32*4)        // cell [jj][b]          128
#define SH_HO (SH_C  + 4*32)          // h out [b][jj]         128
#define SH_TOTAL_FLOATS (SH_HO + 32*4)

extern __shared__ float smem_p[];

__global__ __launch_bounds__(256, 1) void lstm_persist_kernel(
    const float* __restrict__ xpre,
    const float* __restrict__ Whi, const float* __restrict__ Whf,
    const float* __restrict__ Who, const float* __restrict__ Whg,
    const float* __restrict__ c0,
    float* __restrict__ out,
    int write_tail)
{
    float* sh_w  = smem_p + SH_W;
    float* sh_ps = smem_p + SH_PS;
    float* sh_xs = smem_p + SH_XS;
    float* sh_c  = smem_p + SH_C;
    float* sh_ho = smem_p + SH_HO;

    const int tid  = threadIdx.x;
    const int lane = tid & 31;
    const int w    = tid >> 5;
    const int jc   = blockIdx.x * 4;        // h-column base

    // ---- one-time: load weight slice, pair-interleaved ----
    for (int e = tid; e < 8 * 1024; e += 256) {
        int p    = e >> 10;
        int rem  = e & 1023;
        int k    = rem >> 1;
        int half = rem & 1;
        int q    = p >> 1;
        int pp   = p & 1;
        const float* Wq = (q == 0) ? Whi : (q == 1) ? Whf : (q == 2) ? Who : Whg;
        sh_w[p * 1024 + k * 2 + half] = Wq[(size_t)k * HH + jc + pp * 2 + half];
    }
    if (tid < 128) {
        int jj = tid >> 5;
        int b  = tid & 31;
        sh_c[jj * 32 + b] = c0[b * HH + jc + jj];
    }
    __syncthreads();

    const int kb = w * 64;      // this warp's k-slice

    const int g_jj = tid >> 5;
    const int g_b  = tid & 31;
    const int x_b = tid >> 2;
    const int x_q = tid & 3;

    float4 xnext;
    if (tid < 128)
        xnext = *(const float4*)(xpre + ((size_t)x_b * TT + 0) * G4 + x_q * 512 + jc);

    for (int t = 0; t < TT; ++t) {
        const float* hT_r = g_hT[t & 1];
        float*       hT_w = g_hT[(t + 1) & 1];

        // ---- commit staged xpre; prefetch next ----
        if (tid < 128) {
            *(float4*)(sh_xs + (x_q * 32 + x_b) * 4) = xnext;
            if (t + 1 < TT)
                xnext = *(const float4*)(xpre + ((size_t)x_b * TT + t + 1) * G4 + x_q * 512 + jc);
        }

        // ---- preload this warp's entire h slice (64 front-batched LDGs) ----
        const float* hp = hT_r + (size_t)kb * 32 + lane;
        float hr[64];
#pragma unroll
        for (int j = 0; j < 64; j++)
            hr[j] = hp[j * 32];

        // ---- recurrent GEMM slice: pure FFMA2 + LDS broadcast stream ----
        u64t acc[8];
#pragma unroll
        for (int p = 0; p < 8; p++) acc[p] = 0ull;

#pragma unroll
        for (int i = 0; i < 64; i += 2) {
            const int k = kb + i;
            u64t hh0 = pack2(hr[i],     hr[i]);
            u64t hh1 = pack2(hr[i + 1], hr[i + 1]);
#pragma unroll
            for (int p = 0; p < 8; p++) {
                ulonglong2 wv = *(const ulonglong2*)&sh_w[p * 1024 + k * 2];
                acc[p] = ffma2(hh0, wv.x, acc[p]);
                acc[p] = ffma2(hh1, wv.y, acc[p]);
            }
        }
#pragma unroll
        for (int p = 0; p < 8; p++)
            *(u64t*)&sh_ps[w * 512 + p * 64 + lane * 2] = acc[p];
        __syncthreads();

        // ---- gates + state update (128 threads: jj x b) ----
        if (tid < 128) {
            const int jj = g_jj, b = g_b;
            float v[4];
#pragma unroll
            for (int q = 0; q < 4; q++) {
                int p    = q * 2 + (jj >> 1);
                int half = jj & 1;
                float s = sh_xs[(q * 32 + b) * 4 + jj];
#pragma unroll
                for (int w8 = 0; w8 < 8; w8++)
                    s += sh_ps[w8 * 512 + p * 64 + b * 2 + half];
                v[q] = s;
            }
            float it = 1.0f / (1.0f + expf(-v[0]));
            float ft = 1.0f / (1.0f + expf(-v[1]));
            float ot = 1.0f / (1.0f + expf(-v[2]));
            float gt = tanhf(v[3]);
            float cn = ft * sh_c[jj * 32 + b] + it * gt;
            float hn = ot * tanhf(cn);
            sh_c[jj * 32 + b] = cn;
            sh_ho[b * 4 + jj] = hn;
            hT_w[(jc + jj) * BB + b] = hn;     // coalesced 128B per jj
        }
        __syncthreads();

        // ---- arrival, output write, poll (warp 0) ----
        if (tid == 0) {
            __threadfence();
            unsigned a = atomicAdd(&g_bar_count, 1u);
            if (a == (unsigned)(GRID_P - 1)) {
                g_bar_count = 0;
                __threadfence();
                *(volatile unsigned*)&g_bar_phase = (unsigned)(t + 1);
            }
        }
        if (tid < 32) {
            int b = tid;
            *(float4*)(out + ((size_t)b * TT + t) * HH + jc) = *(float4*)(sh_ho + b * 4);
        }
        if (tid == 0) {
            while (*(volatile unsigned*)&g_bar_phase <= (unsigned)t)
                __nanosleep(32);
            __threadfence();
        }
        __syncthreads();
    }

    // ---- final (h_t, c_t) tail ----
    if (write_tail && tid < 128) {
        int jj = tid >> 5;
        int b  = tid & 31;
        const size_t tail = (size_t)BB * TT * HH;
        out[tail + (size_t)b * HH + jc + jj]                   = sh_ho[b * 4 + jj];
        out[tail + (size_t)BB * HH + (size_t)b * HH + jc + jj] = sh_c[jj * 32 + b];
    }
}

// ---------------- launch ----------------
extern "C" void kernel_launch(void* const* d_in, const int* in_sizes, int n_in,
                              void* d_out, int out_size) {
    const float* x   = (const float*)d_in[0];
    const float* h0  = (const float*)d_in[1];
    const float* c0  = (const float*)d_in[2];
    const float* Wii = (const float*)d_in[3];
    const float* Wif = (const float*)d_in[4];
    const float* Wio = (const float*)d_in[5];
    const float* Wig = (const float*)d_in[6];
    const float* Whi = (const float*)d_in[7];
    const float* Whf = (const float*)d_in[8];
    const float* Who = (const float*)d_in[9];
    const float* Whg = (const float*)d_in[10];
    const float* bi  = (const float*)d_in[11];
    const float* bf_ = (const float*)d_in[12];
    const float* bo  = (const float*)d_in[13];
    const float* bg  = (const float*)d_in[14];
    float* out = (float*)d_out;

    float* xpre;
    cudaGetSymbolAddress((void**)&xpre, g_xpre);

    const size_t smem_bytes = SH_TOTAL_FLOATS * sizeof(float);
    cudaFuncSetAttribute(lstm_persist_kernel,
                         cudaFuncAttributeMaxDynamicSharedMemorySize,
                         (int)smem_bytes);

    const long long tail = (long long)BB * TT * HH;
    const int write_tail = ((long long)out_size >= tail + 2LL * BB * HH) ? 1 : 0;

    gemm_x_kernel<<<dim3(256, 16), 256>>>(x, Wii, Wif, Wio, Wig, bi, bf_, bo, bg, h0, xpre);
    lstm_persist_kernel<<<GRID_P, 256, smem_bytes>>>(
        xpre, Whi, Whf, Who, Whg, c0, out, write_tail);
}

// round 6
// speedup vs baseline: 2.0586x; 1.1228x over previous
#include <cuda_runtime.h>
#include <math.h>

#define BB 32
#define TT 1024
#define II 512
#define HH 512
#define G4 2048      // 4*H
#define GRID_P 128   // persistent CTAs (<=148 -> co-resident, deadlock-free)

typedef unsigned long long u64t;

// ---- packed fp32x2 helpers (Blackwell FFMA2) ----
__device__ __forceinline__ u64t ffma2(u64t a, u64t b, u64t c) {
    u64t d;
    asm("fma.rn.f32x2 %0, %1, %2, %3;" : "=l"(d) : "l"(a), "l"(b), "l"(c));
    return d;
}
__device__ __forceinline__ u64t pack2(float x, float y) {
    u64t d;
    asm("mov.b64 %0, {%1, %2};" : "=l"(d) : "f"(x), "f"(y));
    return d;
}
__device__ __forceinline__ float2 unpack2(u64t v) {
    float2 r;
    asm("mov.b64 {%0, %1}, %2;" : "=f"(r.x), "=f"(r.y) : "l"(v));
    return r;
}
// L2-coherent 16B load (bypasses non-coherent L1 for cross-CTA h traffic)
__device__ __forceinline__ void ldcg2(const float* p, u64t& a, u64t& b) {
    asm volatile("ld.global.cg.v2.u64 {%0,%1}, [%2];" : "=l"(a), "=l"(b) : "l"(p));
}

// ---------------- scratch (static device globals; no allocation) ----------------
__device__ float    g_xpre[(size_t)BB * TT * G4];   // [B][T][4H]  256 MB
__device__ float    g_hT[2][HH * BB];               // double-buffered h^T [k][b]
__device__ unsigned g_bar_count;
__device__ unsigned g_bar_phase;

// ---------------- Kernel 1: x_pre = x @ [Wii|Wif|Wio|Wig] + bias ----------------
// Tiled FP32 SGEMM (FFMA2), double-buffered SMEM + register prefetch.
// Block (0,0) additionally performs the init work (h0 -> hT[0], barrier reset).
__global__ __launch_bounds__(256) void gemm_x_kernel(
    const float* __restrict__ X,
    const float* __restrict__ Wii, const float* __restrict__ Wif,
    const float* __restrict__ Wio, const float* __restrict__ Wig,
    const float* __restrict__ bi, const float* __restrict__ bf,
    const float* __restrict__ bo, const float* __restrict__ bg,
    const float* __restrict__ h0,
    float* __restrict__ xpre)
{
    const int mtile = blockIdx.x;          // 0..255
    const int gtile = blockIdx.y;          // 0..15
    const int gate  = gtile >> 2;
    const int j0    = (gtile & 3) * 128;

    if (mtile == 0 && gtile == 0) {
        for (int i = threadIdx.x; i < BB * HH; i += 256) {
            int b = i >> 9;
            int j = i & 511;
            g_hT[0][j * BB + b] = h0[i];
        }
        if (threadIdx.x == 0) { g_bar_count = 0; g_bar_phase = 0; }
    }

    const float* W    = (gate == 0) ? Wii : (gate == 1) ? Wif : (gate == 2) ? Wio : Wig;
    const float* bias = (gate == 0) ? bi  : (gate == 1) ? bf  : (gate == 2) ? bo  : bg;

    __shared__ float As[2][8][132];
    __shared__ float Bs[2][8][128];

    const int tid = threadIdx.x;
    const int tx = tid & 15;
    const int ty = tid >> 4;
    const int m0 = mtile * 128;

    const int a_row = tid >> 1;
    const int a_k   = (tid & 1) * 4;
    const int b_k = tid >> 5;
    const int b_n = (tid & 31) * 4;

    u64t acc2[8][4];
#pragma unroll
    for (int i = 0; i < 8; i++)
#pragma unroll
        for (int j = 0; j < 4; j++) acc2[i][j] = 0ull;

    {
        float4 av = *(const float4*)(X + (size_t)(m0 + a_row) * 512 + a_k);
        As[0][a_k + 0][a_row] = av.x;
        As[0][a_k + 1][a_row] = av.y;
        As[0][a_k + 2][a_row] = av.z;
        As[0][a_k + 3][a_row] = av.w;
        float4 bv = *(const float4*)(W + (size_t)b_k * 512 + j0 + b_n);
        *(float4*)&Bs[0][b_k][b_n] = bv;
    }
    __syncthreads();

    for (int k0 = 0; k0 < 512; k0 += 8) {
        const int cur = (k0 >> 3) & 1;
        const int nxt = cur ^ 1;

        float4 av, bv;
        const bool more = (k0 + 8 < 512);
        if (more) {
            av = *(const float4*)(X + (size_t)(m0 + a_row) * 512 + k0 + 8 + a_k);
            bv = *(const float4*)(W + (size_t)(k0 + 8 + b_k) * 512 + j0 + b_n);
        }

#pragma unroll
        for (int kk = 0; kk < 8; kk++) {
            float4 a0 = *(const float4*)&As[cur][kk][ty * 8];
            float4 a1 = *(const float4*)&As[cur][kk][ty * 8 + 4];
            u64t arr[8];
            arr[0] = pack2(a0.x, a0.x); arr[1] = pack2(a0.y, a0.y);
            arr[2] = pack2(a0.z, a0.z); arr[3] = pack2(a0.w, a0.w);
            arr[4] = pack2(a1.x, a1.x); arr[5] = pack2(a1.y, a1.y);
            arr[6] = pack2(a1.z, a1.z); arr[7] = pack2(a1.w, a1.w);
            ulonglong2 bb0 = *(const ulonglong2*)&Bs[cur][kk][tx * 8];
            ulonglong2 bb1 = *(const ulonglong2*)&Bs[cur][kk][tx * 8 + 4];
            u64t br2[4];
            br2[0] = bb0.x; br2[1] = bb0.y; br2[2] = bb1.x; br2[3] = bb1.y;
#pragma unroll
            for (int i = 0; i < 8; i++)
#pragma unroll
                for (int j = 0; j < 4; j++)
                    acc2[i][j] = ffma2(arr[i], br2[j], acc2[i][j]);
        }

        if (more) {
            As[nxt][a_k + 0][a_row] = av.x;
            As[nxt][a_k + 1][a_row] = av.y;
            As[nxt][a_k + 2][a_row] = av.z;
            As[nxt][a_k + 3][a_row] = av.w;
            *(float4*)&Bs[nxt][b_k][b_n] = bv;
        }
        __syncthreads();
    }

#pragma unroll
    for (int i = 0; i < 8; i++) {
        const size_t m = (size_t)(m0 + ty * 8 + i);
        float* dst = xpre + m * G4 + gate * 512 + j0 + tx * 8;
        float4 o0, o1;
        float2 p0 = unpack2(acc2[i][0]);
        float2 p1 = unpack2(acc2[i][1]);
        float2 p2 = unpack2(acc2[i][2]);
        float2 p3 = unpack2(acc2[i][3]);
        o0.x = p0.x + bias[j0 + tx * 8 + 0];
        o0.y = p0.y + bias[j0 + tx * 8 + 1];
        o0.z = p1.x + bias[j0 + tx * 8 + 2];
        o0.w = p1.y + bias[j0 + tx * 8 + 3];
        o1.x = p2.x + bias[j0 + tx * 8 + 4];
        o1.y = p2.y + bias[j0 + tx * 8 + 5];
        o1.z = p3.x + bias[j0 + tx * 8 + 6];
        o1.w = p3.y + bias[j0 + tx * 8 + 7];
        *(float4*)dst       = o0;
        *(float4*)(dst + 4) = o1;
    }
}

// ---------------- Kernel 2: persistent recurrence ----------------
// 128 CTAs x 256 threads. CTA owns 4 h-cols jc..jc+3 -> 16 gate-cols.
// Warp w: k-slice [w*64, w*64+64). Lane = kh*16 + gco*4 + bq:
//   bq  (0..3): 8 batches  [bq*8, bq*8+8)  (4 FFMA2 b-pairs)
//   gco (0..3): 4 gate-cols [gco*4, gco*4+4)
//   kh  (0..1): k sub-slice of 32
// Weights: SMEM [k][gc] — one LDS.128 per k delivers 4 DISTINCT gate-cols.
// h: direct ld.global.cg (L2-coherent), double-buffered 4-k register chunks.
//
// SMEM layout (floats):
#define SH_W  0                        // w [k][gc]            512*16 = 8192
#define SH_PS (SH_W  + 512*16)         // partials [ws16][gc][b] 16*16*32 = 8192
#define SH_XS (SH_PS + 16*512)         // xpre [q][b][jj]      4*32*4 = 512
#define SH_C  (SH_XS + 4*32*4)         // cell [jj][b]         128
#define SH_HO (SH_C  + 4*32)           // h out [b][jj]        128
#define SH_TOTAL_FLOATS (SH_HO + 32*4)

extern __shared__ float smem_p[];

__global__ __launch_bounds__(256, 1) void lstm_persist_kernel(
    const float* __restrict__ xpre,
    const float* __restrict__ Whi, const float* __restrict__ Whf,
    const float* __restrict__ Who, const float* __restrict__ Whg,
    const float* __restrict__ c0,
    float* __restrict__ out,
    int write_tail)
{
    float* sh_w  = smem_p + SH_W;
    float* sh_ps = smem_p + SH_PS;
    float* sh_xs = smem_p + SH_XS;
    float* sh_c  = smem_p + SH_C;
    float* sh_ho = smem_p + SH_HO;

    const int tid  = threadIdx.x;
    const int lane = tid & 31;
    const int w    = tid >> 5;
    const int jc   = blockIdx.x * 4;        // h-column base

    const int bq  = lane & 3;
    const int gco = (lane >> 2) & 3;
    const int kh  = lane >> 4;

    // ---- one-time: load weight slice [k][gc], gc = q*4 + jj ----
    for (int e = tid; e < 512 * 16; e += 256) {
        int k   = e >> 4;
        int gcl = e & 15;
        int q   = gcl >> 2;
        int jj  = gcl & 3;
        const float* Wq = (q == 0) ? Whi : (q == 1) ? Whf : (q == 2) ? Who : Whg;
        sh_w[e] = Wq[(size_t)k * HH + jc + jj];
    }
    if (tid < 128) {
        int jj = tid >> 5;
        int b  = tid & 31;
        sh_c[jj * 32 + b] = c0[b * HH + jc + jj];
    }
    __syncthreads();

    const int kb = w * 64;                 // warp k-slice base
    const int lane_k0 = kb + kh * 32;      // lane's first k (32 k's)

    const int g_jj = tid >> 5;
    const int g_b  = tid & 31;
    const int x_b = tid >> 2;
    const int x_q = tid & 3;

    float4 xnext;
    if (tid < 128)
        xnext = *(const float4*)(xpre + ((size_t)x_b * TT + 0) * G4 + x_q * 512 + jc);

    for (int t = 0; t < TT; ++t) {
        const float* hT_r = g_hT[t & 1];
        float*       hT_w = g_hT[(t + 1) & 1];

        // ---- commit staged xpre; prefetch next ----
        if (tid < 128) {
            *(float4*)(sh_xs + (x_q * 32 + x_b) * 4) = xnext;
            if (t + 1 < TT)
                xnext = *(const float4*)(xpre + ((size_t)x_b * TT + t + 1) * G4 + x_q * 512 + jc);
        }

        // ---- recurrent GEMM slice ----
        // acc[bp][g]: b-pair bp (2 batches) x gate-col g, over lane's 32 k's
        u64t acc[4][4];
#pragma unroll
        for (int i = 0; i < 4; i++)
#pragma unroll
            for (int j = 0; j < 4; j++) acc[i][j] = 0ull;

        const float* hlane = hT_r + (size_t)lane_k0 * BB + bq * 8;
        const float* wrow  = sh_w + lane_k0 * 16 + gco * 4;

        u64t bufA[16], bufB[16];
        // prefetch chunk 0 (k offsets 0..3)
#pragma unroll
        for (int j = 0; j < 4; j++) {
            ldcg2(hlane + j * BB,     bufA[j * 4 + 0], bufA[j * 4 + 1]);
            ldcg2(hlane + j * BB + 4, bufA[j * 4 + 2], bufA[j * 4 + 3]);
        }

#pragma unroll
        for (int c = 0; c < 8; c++) {
            u64t* cur = (c & 1) ? bufB : bufA;
            u64t* nxt = (c & 1) ? bufA : bufB;
            if (c < 7) {
                const float* hp2 = hlane + (size_t)(c + 1) * 4 * BB;
#pragma unroll
                for (int j = 0; j < 4; j++) {
                    ldcg2(hp2 + j * BB,     nxt[j * 4 + 0], nxt[j * 4 + 1]);
                    ldcg2(hp2 + j * BB + 4, nxt[j * 4 + 2], nxt[j * 4 + 3]);
                }
            }
#pragma unroll
            for (int j = 0; j < 4; j++) {
                const int kk = c * 4 + j;
                ulonglong2 wv = *(const ulonglong2*)(wrow + kk * 16);
                float2 w01 = unpack2(wv.x);
                float2 w23 = unpack2(wv.y);
                u64t ws0 = pack2(w01.x, w01.x);
                u64t ws1 = pack2(w01.y, w01.y);
                u64t ws2 = pack2(w23.x, w23.x);
                u64t ws3 = pack2(w23.y, w23.y);
                u64t h0 = cur[j * 4 + 0];
                u64t h1 = cur[j * 4 + 1];
                u64t h2 = cur[j * 4 + 2];
                u64t h3 = cur[j * 4 + 3];
                acc[0][0] = ffma2(h0, ws0, acc[0][0]);
                acc[0][1] = ffma2(h0, ws1, acc[0][1]);
                acc[0][2] = ffma2(h0, ws2, acc[0][2]);
                acc[0][3] = ffma2(h0, ws3, acc[0][3]);
                acc[1][0] = ffma2(h1, ws0, acc[1][0]);
                acc[1][1] = ffma2(h1, ws1, acc[1][1]);
                acc[1][2] = ffma2(h1, ws2, acc[1][2]);
                acc[1][3] = ffma2(h1, ws3, acc[1][3]);
                acc[2][0] = ffma2(h2, ws0, acc[2][0]);
                acc[2][1] = ffma2(h2, ws1, acc[2][1]);
                acc[2][2] = ffma2(h2, ws2, acc[2][2]);
                acc[2][3] = ffma2(h2, ws3, acc[2][3]);
                acc[3][0] = ffma2(h3, ws0, acc[3][0]);
                acc[3][1] = ffma2(h3, ws1, acc[3][1]);
                acc[3][2] = ffma2(h3, ws2, acc[3][2]);
                acc[3][3] = ffma2(h3, ws3, acc[3][3]);
            }
        }

        // ---- write partials: slot ws16 = w*2 + kh ----
        {
            float* ps = sh_ps + (size_t)(w * 2 + kh) * 512;
#pragma unroll
            for (int g = 0; g < 4; g++)
#pragma unroll
                for (int bp = 0; bp < 4; bp++)
                    *(u64t*)&ps[(gco * 4 + g) * 32 + bq * 8 + bp * 2] = acc[bp][g];
        }
        __syncthreads();

        // ---- gates + state update (128 threads: jj x b) ----
        if (tid < 128) {
            const int jj = g_jj, b = g_b;
            float v[4];
#pragma unroll
            for (int q = 0; q < 4; q++) {
                float s = sh_xs[(q * 32 + b) * 4 + jj];
                const int gc = q * 4 + jj;
#pragma unroll
                for (int ws16 = 0; ws16 < 16; ws16++)
                    s += sh_ps[ws16 * 512 + gc * 32 + b];
                v[q] = s;
            }
            float it = 1.0f / (1.0f + expf(-v[0]));
            float ft = 1.0f / (1.0f + expf(-v[1]));
            float ot = 1.0f / (1.0f + expf(-v[2]));
            float gt = tanhf(v[3]);
            float cn = ft * sh_c[jj * 32 + b] + it * gt;
            float hn = ot * tanhf(cn);
            sh_c[jj * 32 + b] = cn;
            sh_ho[b * 4 + jj] = hn;
            hT_w[(jc + jj) * BB + b] = hn;     // coalesced 128B per jj
        }
        __syncthreads();

        // ---- arrival, output write, poll (warp 0) ----
        if (tid == 0) {
            __threadfence();
            unsigned a = atomicAdd(&g_bar_count, 1u);
            if (a == (unsigned)(GRID_P - 1)) {
                g_bar_count = 0;
                __threadfence();
                *(volatile unsigned*)&g_bar_phase = (unsigned)(t + 1);
            }
        }
        if (tid < 32) {
            int b = tid;
            *(float4*)(out + ((size_t)b * TT + t) * HH + jc) = *(float4*)(sh_ho + b * 4);
        }
        if (tid == 0) {
            while (*(volatile unsigned*)&g_bar_phase <= (unsigned)t)
                __nanosleep(32);
            __threadfence();
        }
        __syncthreads();
    }

    // ---- final (h_t, c_t) tail ----
    if (write_tail && tid < 128) {
        int jj = tid >> 5;
        int b  = tid & 31;
        const size_t tail = (size_t)BB * TT * HH;
        out[tail + (size_t)b * HH + jc + jj]                   = sh_ho[b * 4 + jj];
        out[tail + (size_t)BB * HH + (size_t)b * HH + jc + jj] = sh_c[jj * 32 + b];
    }
}

// ---------------- launch ----------------
extern "C" void kernel_launch(void* const* d_in, const int* in_sizes, int n_in,
                              void* d_out, int out_size) {
    const float* x   = (const float*)d_in[0];
    const float* h0  = (const float*)d_in[1];
    const float* c0  = (const float*)d_in[2];
    const float* Wii = (const float*)d_in[3];
    const float* Wif = (const float*)d_in[4];
    const float* Wio = (const float*)d_in[5];
    const float* Wig = (const float*)d_in[6];
    const float* Whi = (const float*)d_in[7];
    const float* Whf = (const float*)d_in[8];
    const float* Who = (const float*)d_in[9];
    const float* Whg = (const float*)d_in[10];
    const float* bi  = (const float*)d_in[11];
    const float* bf_ = (const float*)d_in[12];
    const float* bo  = (const float*)d_in[13];
    const float* bg  = (const float*)d_in[14];
    float* out = (float*)d_out;

    float* xpre;
    cudaGetSymbolAddress((void**)&xpre, g_xpre);

    const size_t smem_bytes = SH_TOTAL_FLOATS * sizeof(float);
    cudaFuncSetAttribute(lstm_persist_kernel,
                         cudaFuncAttributeMaxDynamicSharedMemorySize,
                         (int)smem_bytes);

    const long long tail = (long long)BB * TT * HH;
    const int write_tail = ((long long)out_size >= tail + 2LL * BB * HH) ? 1 : 0;

    gemm_x_kernel<<<dim3(256, 16), 256>>>(x, Wii, Wif, Wio, Wig, bi, bf_, bo, bg, h0, xpre);
    lstm_persist_kernel<<<GRID_P, 256, smem_bytes>>>(
        xpre, Whi, Whf, Who, Whg, c0, out, write_tail);
}